// round 13
// baseline (speedup 1.0000x reference)
#include <cuda_runtime.h>
#include <cuda_fp16.h>

#define N_NODES  50000
#define N_EDGES  800000
#define N_GRAPHS 128
#define HID      64
#define VOCAB    100
#define LAYERS   3
#define NPB      128                          // nodes per block in mlp kernel
#define CSR_CAP  (N_EDGES + 7 * N_NODES)      // padded CSR capacity
#define SCAN_BLKS ((N_NODES + 1023) / 1024)   // 49

// Scratch (__device__ globals — allocation-free rule).
// Row N_NODES of g_hh and row VOCAB of g_embh are permanent ZERO rows
// (never written): padded-CSR dummy gather targets.
// g_deg invariant: zero at entry (static init; scan_kernel re-zeros).
__device__ __half g_hh[(N_NODES + 1) * HID];   // fp16 inter-layer h (128B/row)
__device__ __half g_zh[N_NODES * HID];         // fp16 aggregated z (128B/row)
__device__ __half g_embh[(VOCAB + 1) * HID];   // fp16 embedding (L1-resident)
__device__ __half g_w1h[LAYERS * HID * HID];   // fp16 W1
__device__ __half g_w2h[LAYERS * HID * HID];   // fp16 W2
__device__ int    g_feats_pad[N_NODES + 1];
__device__ int    g_deg[N_NODES];
__device__ int    g_rowptr[N_NODES + 1];
__device__ int    g_pos[N_NODES];
__device__ int    g_blk_agg[SCAN_BLKS];
__device__ int2   g_csr[CSR_CAP];              // (src, feat[src]) per edge

__device__ __forceinline__ unsigned su32(const void* p) {
    return (unsigned)__cvta_generic_to_shared(p);
}

// ---------------------------------------------------------------------------
// Setup: CSR pad-fill + degree hist + fp16 emb/W1/W2 + padded feats + zeroing
// ---------------------------------------------------------------------------
__global__ void setup_kernel(const int* __restrict__ dst,
                             const int* __restrict__ feats,
                             const float* __restrict__ emb,
                             const float* __restrict__ W1,
                             const float* __restrict__ W2,
                             float* __restrict__ out) {
    int i = blockIdx.x * blockDim.x + threadIdx.x;
    if (i * 4 < CSR_CAP) {
        int4 pad = make_int4(N_NODES, VOCAB, N_NODES, VOCAB);
        ((int4*)g_csr)[2 * i]     = pad;
        ((int4*)g_csr)[2 * i + 1] = pad;
    }
    if (i * 4 < N_EDGES) {
        int4 d = ((const int4*)dst)[i];
        atomicAdd(&g_deg[d.x], 1);
        atomicAdd(&g_deg[d.y], 1);
        atomicAdd(&g_deg[d.z], 1);
        atomicAdd(&g_deg[d.w], 1);
    }
    if (i < (VOCAB + 1) * HID)
        g_embh[i] = __float2half_rn((i < VOCAB * HID) ? emb[i] : 0.f);
    if (i < LAYERS * HID * HID) {
        g_w1h[i] = __float2half_rn(W1[i]);
        g_w2h[i] = __float2half_rn(W2[i]);
    }
    if (i < N_NODES)       g_feats_pad[i] = __ldg(feats + i);
    else if (i == N_NODES) g_feats_pad[i] = VOCAB;
    if (i < SCAN_BLKS) g_blk_agg[i] = 0;
    if (i < N_GRAPHS)  out[i] = 0.f;
}

// ---------------------------------------------------------------------------
// Single-pass scan of PADDED degrees (x8) -> rowptr + pos; re-zeros g_deg.
// 49 blocks all resident in one wave -> spin on predecessor aggregates safe.
// ---------------------------------------------------------------------------
__global__ void __launch_bounds__(1024) scan_kernel() {
    __shared__ int warp_sums[32];
    __shared__ int block_prefix;
    const int t = threadIdx.x, b = blockIdx.x;
    const int lane = t & 31, warp = t >> 5;
    if (t == 0) block_prefix = 0;

    int i = b * 1024 + t;
    int d = 0;
    if (i < N_NODES) {
        d = (g_deg[i] + 7) & ~7;
        g_deg[i] = 0;
    }

    int incl = d;
#pragma unroll
    for (int off = 1; off < 32; off <<= 1) {
        int u = __shfl_up_sync(0xffffffffu, incl, off);
        if (lane >= off) incl += u;
    }
    if (lane == 31) warp_sums[warp] = incl;
    __syncthreads();

    if (warp == 0) {
        int v = warp_sums[lane];
        int w = v;
#pragma unroll
        for (int off = 1; off < 32; off <<= 1) {
            int u = __shfl_up_sync(0xffffffffu, w, off);
            if (lane >= off) w += u;
        }
        warp_sums[lane] = w;
    }
    __syncthreads();

    int wexcl = (warp > 0) ? warp_sums[warp - 1] : 0;
    int excl  = wexcl + incl - d;
    int block_total = warp_sums[31];

    if (t == 0)
        *(volatile int*)&g_blk_agg[b] = block_total + 1;

    if (t < b) {
        int v;
        do { v = *(volatile int*)&g_blk_agg[t]; } while (v == 0);
        atomicAdd(&block_prefix, v - 1);
    }
    __syncthreads();

    int r = block_prefix + excl;
    if (i < N_NODES) {
        g_rowptr[i] = r;
        g_pos[i]    = r;
    }
    if (b == SCAN_BLKS - 1 && t == 1023)
        g_rowptr[N_NODES] = block_prefix + excl + d;
}

// ---------------------------------------------------------------------------
// Scatter: one 8B (src, feat) store per edge into the merged CSR.
// ---------------------------------------------------------------------------
__global__ void scatter_kernel(const int* __restrict__ src,
                               const int* __restrict__ dst) {
    int i = blockIdx.x * blockDim.x + threadIdx.x;
    if (i * 4 >= N_EDGES) return;
    int4 s = ((const int4*)src)[i];
    int4 d = ((const int4*)dst)[i];
    int f0 = __ldg(&g_feats_pad[s.x]);
    int f1 = __ldg(&g_feats_pad[s.y]);
    int f2 = __ldg(&g_feats_pad[s.z]);
    int f3 = __ldg(&g_feats_pad[s.w]);
    int p;
    p = atomicAdd(&g_pos[d.x], 1); g_csr[p] = make_int2(s.x, f0);
    p = atomicAdd(&g_pos[d.y], 1); g_csr[p] = make_int2(s.y, f1);
    p = atomicAdd(&g_pos[d.z], 1); g_csr[p] = make_int2(s.z, f2);
    p = atomicAdd(&g_pos[d.w], 1); g_csr[p] = make_int2(s.w, f3);
}

// ---------------------------------------------------------------------------
// Unified aggregation, TEMPLATED on MODE (compile-time: no per-batch selects):
//   MODE=1: z[n] = embh[feat[n]] + sum embh[csr[e].y]
//   MODE=0: z[n] = hh[n]        + sum hh[csr[e].x]
// 4 threads/node, each owns TWO uint4 slots (c, c+4) = 32B of the 128B row.
// Halves redundant index loads vs 8-thr/node; 200k threads = ~1 wave.
// fp32 accumulate, fp16 z out. Padded CSR rows (x8) -> no remainder.
// ---------------------------------------------------------------------------
__device__ __forceinline__ void acc8h(float4& A, float4& B, uint4 u) {
    float2 f;
    f = __half22float2(*(const __half2*)&u.x); A.x += f.x; A.y += f.y;
    f = __half22float2(*(const __half2*)&u.y); A.z += f.x; A.w += f.y;
    f = __half22float2(*(const __half2*)&u.z); B.x += f.x; B.y += f.y;
    f = __half22float2(*(const __half2*)&u.w); B.z += f.x; B.w += f.y;
}

template <int MODE>
__global__ void __launch_bounds__(256)
agg_kernel_t() {
    int i = blockIdx.x * blockDim.x + threadIdx.x;
    if (i >= N_NODES * 4) return;
    int n = i >> 2;
    int c = i & 3;                      // owns uint4 slots c and c+4
    const uint4* tab = MODE ? (const uint4*)g_embh : (const uint4*)g_hh;

    float4 A0 = {0,0,0,0}, B0 = {0,0,0,0};
    float4 A1 = {0,0,0,0}, B1 = {0,0,0,0};

    int self = MODE ? __ldg(&g_feats_pad[n]) : n;
    acc8h(A0, B0, tab[self * 8 + c]);
    acc8h(A1, B1, tab[self * 8 + c + 4]);

    int e   = __ldg(&g_rowptr[n]);
    int end = __ldg(&g_rowptr[n + 1]);
    for (; e < end; e += 8) {
        int4 p0 = *(const int4*)&g_csr[e];       // (s,f, s,f) edges e,e+1
        int4 p1 = *(const int4*)&g_csr[e + 2];
        int4 p2 = *(const int4*)&g_csr[e + 4];
        int4 p3 = *(const int4*)&g_csr[e + 6];
        int s0 = MODE ? p0.y : p0.x;
        int s1 = MODE ? p0.w : p0.z;
        int s2 = MODE ? p1.y : p1.x;
        int s3 = MODE ? p1.w : p1.z;
        int s4 = MODE ? p2.y : p2.x;
        int s5 = MODE ? p2.w : p2.z;
        int s6 = MODE ? p3.y : p3.x;
        int s7 = MODE ? p3.w : p3.z;
        uint4 u0a = tab[s0 * 8 + c], u0b = tab[s0 * 8 + c + 4];
        uint4 u1a = tab[s1 * 8 + c], u1b = tab[s1 * 8 + c + 4];
        uint4 u2a = tab[s2 * 8 + c], u2b = tab[s2 * 8 + c + 4];
        uint4 u3a = tab[s3 * 8 + c], u3b = tab[s3 * 8 + c + 4];
        uint4 u4a = tab[s4 * 8 + c], u4b = tab[s4 * 8 + c + 4];
        uint4 u5a = tab[s5 * 8 + c], u5b = tab[s5 * 8 + c + 4];
        uint4 u6a = tab[s6 * 8 + c], u6b = tab[s6 * 8 + c + 4];
        uint4 u7a = tab[s7 * 8 + c], u7b = tab[s7 * 8 + c + 4];
        acc8h(A0, B0, u0a); acc8h(A1, B1, u0b);
        acc8h(A0, B0, u1a); acc8h(A1, B1, u1b);
        acc8h(A0, B0, u2a); acc8h(A1, B1, u2b);
        acc8h(A0, B0, u3a); acc8h(A1, B1, u3b);
        acc8h(A0, B0, u4a); acc8h(A1, B1, u4b);
        acc8h(A0, B0, u5a); acc8h(A1, B1, u5b);
        acc8h(A0, B0, u6a); acc8h(A1, B1, u6b);
        acc8h(A0, B0, u7a); acc8h(A1, B1, u7b);
    }

    {
        __half2 q0 = __floats2half2_rn(A0.x, A0.y);
        __half2 q1 = __floats2half2_rn(A0.z, A0.w);
        __half2 q2 = __floats2half2_rn(B0.x, B0.y);
        __half2 q3 = __floats2half2_rn(B0.z, B0.w);
        ((uint4*)g_zh)[n * 8 + c] = make_uint4(*(unsigned*)&q0, *(unsigned*)&q1,
                                               *(unsigned*)&q2, *(unsigned*)&q3);
        __half2 r0 = __floats2half2_rn(A1.x, A1.y);
        __half2 r1 = __floats2half2_rn(A1.z, A1.w);
        __half2 r2 = __floats2half2_rn(B1.x, B1.y);
        __half2 r3 = __floats2half2_rn(B1.z, B1.w);
        ((uint4*)g_zh)[n * 8 + c + 4] = make_uint4(*(unsigned*)&r0, *(unsigned*)&r1,
                                                   *(unsigned*)&r2, *(unsigned*)&r3);
    }
}

// ---------------------------------------------------------------------------
// MLP via tensor cores (HMMA m16n8k16, fp16 in / fp32 accum):
//   h = relu(z@W1+b1)@W2 + b2.
// 128 threads (4 warps), 128 nodes/block. Warp owns 32 rows x 64 cols.
// GEMM1 C-regs -> relu -> fp16 A-fragments for GEMM2 IN REGISTERS.
// LAST layer: fused pool+head.
// ---------------------------------------------------------------------------
#define WS 72   // padded row stride in halves (144B -> conflict-free ldmatrix)

#define LDSM_X4(r0, r1, r2, r3, a) \
    asm volatile("ldmatrix.sync.aligned.m8n8.x4.shared.b16 {%0,%1,%2,%3}, [%4];" \
                 : "=r"(r0), "=r"(r1), "=r"(r2), "=r"(r3) : "r"(a))
#define LDSM_X4T(r0, r1, r2, r3, a) \
    asm volatile("ldmatrix.sync.aligned.m8n8.x4.trans.shared.b16 {%0,%1,%2,%3}, [%4];" \
                 : "=r"(r0), "=r"(r1), "=r"(r2), "=r"(r3) : "r"(a))
#define MMA16816(c, a, b) \
    asm volatile("mma.sync.aligned.m16n8k16.row.col.f32.f16.f16.f32 " \
                 "{%0,%1,%2,%3}, {%4,%5,%6,%7}, {%8,%9}, {%0,%1,%2,%3};" \
                 : "+f"((c)[0]), "+f"((c)[1]), "+f"((c)[2]), "+f"((c)[3]) \
                 : "r"((a)[0]), "r"((a)[1]), "r"((a)[2]), "r"((a)[3]), \
                   "r"((b)[0]), "r"((b)[1]))

__global__ void __launch_bounds__(128)
mlp_kernel(const float* __restrict__ b1, const float* __restrict__ b2,
           int layer, int last,
           const int* __restrict__ gids, const float* __restrict__ Wr,
           float* __restrict__ out) {
    __shared__ __align__(16) __half sW1[HID * WS];
    __shared__ __align__(16) __half sW2[HID * WS];
    __shared__ __align__(16) __half sZ[NPB * WS];

    const int tid  = threadIdx.x;
    const int lane = tid & 31;
    const int w    = tid >> 5;
    const int nbase = blockIdx.x * NPB;

    // ---- stage fp16 weights (padded rows) ----
    {
        const uint4* w1g = (const uint4*)(g_w1h + layer * HID * HID);
        const uint4* w2g = (const uint4*)(g_w2h + layer * HID * HID);
#pragma unroll
        for (int idx = tid; idx < 512; idx += 128) {
            int r = idx >> 3, c = idx & 7;
            *(uint4*)&sW1[r * WS + c * 8] = w1g[idx];
            *(uint4*)&sW2[r * WS + c * 8] = w2g[idx];
        }
    }
    // ---- stage z tile (one 128B row per thread) ----
    {
        int n = nbase + tid;
        if (n < N_NODES) {
            const uint4* zr = (const uint4*)(g_zh + n * HID);
#pragma unroll
            for (int q = 0; q < 8; q++)
                *(uint4*)&sZ[tid * WS + q * 8] = zr[q];
        } else {
            uint4 zz = make_uint4(0u, 0u, 0u, 0u);
#pragma unroll
            for (int q = 0; q < 8; q++)
                *(uint4*)&sZ[tid * WS + q * 8] = zz;
        }
    }
    __syncthreads();

    const float* b1g = b1 + layer * HID;
    const float* b2g = b2 + layer * HID;

    float acc[2][8][4];
    unsigned ya[2][8][2];   // relu(GEMM1) as fp16 A-fragments

    // ================= GEMM 1: Y = relu(Z @ W1 + b1) =================
#pragma unroll
    for (int nt = 0; nt < 8; nt++) {
        int col = nt * 8 + (lane & 3) * 2;
        float v0 = __ldg(b1g + col), v1 = __ldg(b1g + col + 1);
#pragma unroll
        for (int mt = 0; mt < 2; mt++) {
            acc[mt][nt][0] = v0; acc[mt][nt][1] = v1;
            acc[mt][nt][2] = v0; acc[mt][nt][3] = v1;
        }
    }
#pragma unroll
    for (int ks = 0; ks < 4; ks++) {
        unsigned a[2][4], bf[8][2];
#pragma unroll
        for (int mt = 0; mt < 2; mt++) {
            int row = 32 * w + mt * 16 + (lane & 15);
            int ch  = ks * 16 + ((lane >> 4) << 3);
            LDSM_X4(a[mt][0], a[mt][1], a[mt][2], a[mt][3],
                    su32(&sZ[row * WS + ch]));
        }
#pragma unroll
        for (int ntp = 0; ntp < 4; ntp++) {
            int kr = ks * 16 + (((lane >> 3) & 1) << 3) + (lane & 7);
            int nc = ntp * 16 + ((lane >> 4) << 3);
            LDSM_X4T(bf[2 * ntp][0], bf[2 * ntp][1],
                     bf[2 * ntp + 1][0], bf[2 * ntp + 1][1],
                     su32(&sW1[kr * WS + nc]));
        }
#pragma unroll
        for (int mt = 0; mt < 2; mt++)
#pragma unroll
            for (int nt = 0; nt < 8; nt++)
                MMA16816(acc[mt][nt], a[mt], bf[nt]);
    }
    // relu + pack fp16 (C layout == A layout)
#pragma unroll
    for (int mt = 0; mt < 2; mt++)
#pragma unroll
        for (int nt = 0; nt < 8; nt++) {
            __half2 y0 = __floats2half2_rn(fmaxf(acc[mt][nt][0], 0.f),
                                           fmaxf(acc[mt][nt][1], 0.f));
            __half2 y1 = __floats2half2_rn(fmaxf(acc[mt][nt][2], 0.f),
                                           fmaxf(acc[mt][nt][3], 0.f));
            ya[mt][nt][0] = *(unsigned*)&y0;
            ya[mt][nt][1] = *(unsigned*)&y1;
        }

    // ================= GEMM 2: H = Y @ W2 + b2 =================
#pragma unroll
    for (int nt = 0; nt < 8; nt++) {
        int col = nt * 8 + (lane & 3) * 2;
        float v0 = __ldg(b2g + col), v1 = __ldg(b2g + col + 1);
#pragma unroll
        for (int mt = 0; mt < 2; mt++) {
            acc[mt][nt][0] = v0; acc[mt][nt][1] = v1;
            acc[mt][nt][2] = v0; acc[mt][nt][3] = v1;
        }
    }
#pragma unroll
    for (int kt = 0; kt < 4; kt++) {
        unsigned bf[8][2];
#pragma unroll
        for (int ntp = 0; ntp < 4; ntp++) {
            int kr = kt * 16 + (((lane >> 3) & 1) << 3) + (lane & 7);
            int nc = ntp * 16 + ((lane >> 4) << 3);
            LDSM_X4T(bf[2 * ntp][0], bf[2 * ntp][1],
                     bf[2 * ntp + 1][0], bf[2 * ntp + 1][1],
                     su32(&sW2[kr * WS + nc]));
        }
#pragma unroll
        for (int mt = 0; mt < 2; mt++) {
            unsigned a2[4] = { ya[mt][2 * kt][0],     ya[mt][2 * kt][1],
                               ya[mt][2 * kt + 1][0], ya[mt][2 * kt + 1][1] };
#pragma unroll
            for (int nt = 0; nt < 8; nt++)
                MMA16816(acc[mt][nt], a2, bf[nt]);
        }
    }

    if (!last) {
        // store h fp16: thread owns (row0, row0+8) x col pairs per tile
#pragma unroll
        for (int mt = 0; mt < 2; mt++) {
            int row0 = nbase + 32 * w + mt * 16 + (lane >> 2);
#pragma unroll
            for (int nt = 0; nt < 8; nt++) {
                int col = nt * 8 + (lane & 3) * 2;
                if (row0 < N_NODES) {
                    __half2 v = __floats2half2_rn(acc[mt][nt][0], acc[mt][nt][1]);
                    *(__half2*)&g_hh[row0 * HID + col] = v;
                }
                if (row0 + 8 < N_NODES) {
                    __half2 v = __floats2half2_rn(acc[mt][nt][2], acc[mt][nt][3]);
                    *(__half2*)&g_hh[(row0 + 8) * HID + col] = v;
                }
            }
        }
    } else {
        // fused pool + head: dot rows with Wr, reduce over 4 col-lanes
#pragma unroll
        for (int mt = 0; mt < 2; mt++) {
            float d0 = 0.f, d1 = 0.f;
#pragma unroll
            for (int nt = 0; nt < 8; nt++) {
                int col = nt * 8 + (lane & 3) * 2;
                float wr0 = __ldg(Wr + col), wr1 = __ldg(Wr + col + 1);
                d0 = fmaf(acc[mt][nt][0], wr0, fmaf(acc[mt][nt][1], wr1, d0));
                d1 = fmaf(acc[mt][nt][2], wr0, fmaf(acc[mt][nt][3], wr1, d1));
            }
            d0 += __shfl_xor_sync(0xffffffffu, d0, 1);
            d0 += __shfl_xor_sync(0xffffffffu, d0, 2);
            d1 += __shfl_xor_sync(0xffffffffu, d1, 1);
            d1 += __shfl_xor_sync(0xffffffffu, d1, 2);
            if ((lane & 3) == 0) {
                int row0 = nbase + 32 * w + mt * 16 + (lane >> 2);
                if (row0 < N_NODES)
                    atomicAdd(out + __ldg(gids + row0), d0);
                if (row0 + 8 < N_NODES)
                    atomicAdd(out + __ldg(gids + row0 + 8), d1);
            }
        }
    }
}

// ---------------------------------------------------------------------------
extern "C" void kernel_launch(void* const* d_in, const int* in_sizes, int n_in,
                              void* d_out, int out_size) {
    const int*   feats = (const int*)d_in[0];
    const int*   src   = (const int*)d_in[1];
    const int*   dst   = (const int*)d_in[2];
    const int*   gids  = (const int*)d_in[3];
    const float* emb   = (const float*)d_in[4];
    const float* W1    = (const float*)d_in[5];
    const float* b1    = (const float*)d_in[6];
    const float* W2    = (const float*)d_in[7];
    const float* b2    = (const float*)d_in[8];
    const float* Wr    = (const float*)d_in[9];
    float* out = (float*)d_out;

    // CSR build (padded rows) + prep — 3 kernels
    setup_kernel<<<(CSR_CAP / 4 + 255) / 256, 256>>>(dst, feats, emb, W1, W2, out);
    scan_kernel<<<SCAN_BLKS, 1024>>>();
    scatter_kernel<<<(N_EDGES / 4 + 255) / 256, 256>>>(src, dst);

    // 3 GIN layers
    const int ablk = (N_NODES * 4 + 255) / 256;
    const int mblk = (N_NODES + NPB - 1) / NPB;

    agg_kernel_t<1><<<ablk, 256>>>();
    mlp_kernel<<<mblk, 128>>>(b1, b2, 0, 0, gids, Wr, out);
    agg_kernel_t<0><<<ablk, 256>>>();
    mlp_kernel<<<mblk, 128>>>(b1, b2, 1, 0, gids, Wr, out);
    agg_kernel_t<0><<<ablk, 256>>>();
    mlp_kernel<<<mblk, 128>>>(b1, b2, 2, 1, gids, Wr, out);
}

// round 14
// speedup vs baseline: 1.1135x; 1.1135x over previous
#include <cuda_runtime.h>
#include <cuda_fp16.h>

#define N_NODES  50000
#define N_EDGES  800000
#define N_GRAPHS 128
#define HID      64
#define VOCAB    100
#define LAYERS   3
#define NPB      128                          // nodes per block in mlp kernel
#define CSR_CAP  (N_EDGES + 7 * N_NODES)      // padded CSR capacity
#define SCAN_BLKS ((N_NODES + 1023) / 1024)   // 49

// Scratch (__device__ globals — allocation-free rule).
// Row N_NODES of g_hh and row VOCAB of g_embh are permanent ZERO rows
// (never written): padded-CSR dummy gather targets.
// g_deg invariant: zero at entry (static init; scan_kernel re-zeros).
__device__ __half g_hh[(N_NODES + 1) * HID];   // fp16 inter-layer h (128B/row)
__device__ __half g_zh[N_NODES * HID];         // fp16 aggregated z (128B/row)
__device__ __half g_embh[(VOCAB + 1) * HID];   // fp16 embedding (L1-resident)
__device__ __half g_w1h[LAYERS * HID * HID];   // fp16 W1
__device__ __half g_w2h[LAYERS * HID * HID];   // fp16 W2
__device__ int    g_feats_pad[N_NODES + 1];
__device__ int    g_deg[N_NODES];
__device__ int    g_rowptr[N_NODES + 1];
__device__ int    g_pos[N_NODES];
__device__ int    g_blk_agg[SCAN_BLKS];
__device__ int2   g_csr[CSR_CAP];              // (src, feat[src]) per edge

__device__ __forceinline__ unsigned su32(const void* p) {
    return (unsigned)__cvta_generic_to_shared(p);
}

// ---------------------------------------------------------------------------
// Setup: CSR pad-fill + degree hist + fp16 emb/W1/W2 + padded feats + zeroing
// ---------------------------------------------------------------------------
__global__ void setup_kernel(const int* __restrict__ dst,
                             const int* __restrict__ feats,
                             const float* __restrict__ emb,
                             const float* __restrict__ W1,
                             const float* __restrict__ W2,
                             float* __restrict__ out) {
    int i = blockIdx.x * blockDim.x + threadIdx.x;
    if (i * 4 < CSR_CAP) {
        int4 pad = make_int4(N_NODES, VOCAB, N_NODES, VOCAB);
        ((int4*)g_csr)[2 * i]     = pad;
        ((int4*)g_csr)[2 * i + 1] = pad;
    }
    if (i * 4 < N_EDGES) {
        int4 d = ((const int4*)dst)[i];
        atomicAdd(&g_deg[d.x], 1);
        atomicAdd(&g_deg[d.y], 1);
        atomicAdd(&g_deg[d.z], 1);
        atomicAdd(&g_deg[d.w], 1);
    }
    if (i < (VOCAB + 1) * HID)
        g_embh[i] = __float2half_rn((i < VOCAB * HID) ? emb[i] : 0.f);
    if (i < LAYERS * HID * HID) {
        g_w1h[i] = __float2half_rn(W1[i]);
        g_w2h[i] = __float2half_rn(W2[i]);
    }
    if (i < N_NODES)       g_feats_pad[i] = __ldg(feats + i);
    else if (i == N_NODES) g_feats_pad[i] = VOCAB;
    if (i < SCAN_BLKS) g_blk_agg[i] = 0;
    if (i < N_GRAPHS)  out[i] = 0.f;
}

// ---------------------------------------------------------------------------
// Single-pass scan of PADDED degrees (x8) -> rowptr + pos; re-zeros g_deg.
// 49 blocks all resident in one wave -> spin on predecessor aggregates safe.
// ---------------------------------------------------------------------------
__global__ void __launch_bounds__(1024) scan_kernel() {
    __shared__ int warp_sums[32];
    __shared__ int block_prefix;
    const int t = threadIdx.x, b = blockIdx.x;
    const int lane = t & 31, warp = t >> 5;
    if (t == 0) block_prefix = 0;

    int i = b * 1024 + t;
    int d = 0;
    if (i < N_NODES) {
        d = (g_deg[i] + 7) & ~7;
        g_deg[i] = 0;
    }

    int incl = d;
#pragma unroll
    for (int off = 1; off < 32; off <<= 1) {
        int u = __shfl_up_sync(0xffffffffu, incl, off);
        if (lane >= off) incl += u;
    }
    if (lane == 31) warp_sums[warp] = incl;
    __syncthreads();

    if (warp == 0) {
        int v = warp_sums[lane];
        int w = v;
#pragma unroll
        for (int off = 1; off < 32; off <<= 1) {
            int u = __shfl_up_sync(0xffffffffu, w, off);
            if (lane >= off) w += u;
        }
        warp_sums[lane] = w;
    }
    __syncthreads();

    int wexcl = (warp > 0) ? warp_sums[warp - 1] : 0;
    int excl  = wexcl + incl - d;
    int block_total = warp_sums[31];

    if (t == 0)
        *(volatile int*)&g_blk_agg[b] = block_total + 1;

    if (t < b) {
        int v;
        do { v = *(volatile int*)&g_blk_agg[t]; } while (v == 0);
        atomicAdd(&block_prefix, v - 1);
    }
    __syncthreads();

    int r = block_prefix + excl;
    if (i < N_NODES) {
        g_rowptr[i] = r;
        g_pos[i]    = r;
    }
    if (b == SCAN_BLKS - 1 && t == 1023)
        g_rowptr[N_NODES] = block_prefix + excl + d;
}

// ---------------------------------------------------------------------------
// Scatter: one 8B (src, feat) store per edge into the merged CSR.
// ---------------------------------------------------------------------------
__global__ void scatter_kernel(const int* __restrict__ src,
                               const int* __restrict__ dst) {
    int i = blockIdx.x * blockDim.x + threadIdx.x;
    if (i * 4 >= N_EDGES) return;
    int4 s = ((const int4*)src)[i];
    int4 d = ((const int4*)dst)[i];
    int f0 = __ldg(&g_feats_pad[s.x]);
    int f1 = __ldg(&g_feats_pad[s.y]);
    int f2 = __ldg(&g_feats_pad[s.z]);
    int f3 = __ldg(&g_feats_pad[s.w]);
    int p;
    p = atomicAdd(&g_pos[d.x], 1); g_csr[p] = make_int2(s.x, f0);
    p = atomicAdd(&g_pos[d.y], 1); g_csr[p] = make_int2(s.y, f1);
    p = atomicAdd(&g_pos[d.z], 1); g_csr[p] = make_int2(s.z, f2);
    p = atomicAdd(&g_pos[d.w], 1); g_csr[p] = make_int2(s.w, f3);
}

// ---------------------------------------------------------------------------
// Unified aggregation, TEMPLATED on MODE (compile-time: no per-batch selects).
//   MODE=1: z[n] = embh[feat[n]] + sum embh[csr[e].y]
//   MODE=0: z[n] = hh[n]        + sum hh[csr[e].x]
// 8 threads/node (R12 mapping — best measured), one uint4 (8 halves) each,
// fp32 accumulate, fp16 z out. Padded CSR rows (x8) -> no remainder.
// ---------------------------------------------------------------------------
__device__ __forceinline__ void acc8h(float4& A, float4& B, uint4 u) {
    float2 f;
    f = __half22float2(*(const __half2*)&u.x); A.x += f.x; A.y += f.y;
    f = __half22float2(*(const __half2*)&u.y); A.z += f.x; A.w += f.y;
    f = __half22float2(*(const __half2*)&u.z); B.x += f.x; B.y += f.y;
    f = __half22float2(*(const __half2*)&u.w); B.z += f.x; B.w += f.y;
}

template <int MODE>
__global__ void __launch_bounds__(256)
agg_kernel_t() {
    int i = blockIdx.x * blockDim.x + threadIdx.x;
    if (i >= N_NODES * 8) return;
    int n = i >> 3;
    int c = i & 7;
    const uint4* tab = MODE ? (const uint4*)g_embh : (const uint4*)g_hh;

    float4 A = {0.f, 0.f, 0.f, 0.f}, B = {0.f, 0.f, 0.f, 0.f};
    int self = MODE ? __ldg(&g_feats_pad[n]) : n;
    acc8h(A, B, tab[self * 8 + c]);

    int e   = __ldg(&g_rowptr[n]);
    int end = __ldg(&g_rowptr[n + 1]);
    for (; e < end; e += 8) {
        int4 p0 = *(const int4*)&g_csr[e];       // (s,f, s,f) edges e,e+1
        int4 p1 = *(const int4*)&g_csr[e + 2];
        int4 p2 = *(const int4*)&g_csr[e + 4];
        int4 p3 = *(const int4*)&g_csr[e + 6];
        int s0 = MODE ? p0.y : p0.x;
        int s1 = MODE ? p0.w : p0.z;
        int s2 = MODE ? p1.y : p1.x;
        int s3 = MODE ? p1.w : p1.z;
        int s4 = MODE ? p2.y : p2.x;
        int s5 = MODE ? p2.w : p2.z;
        int s6 = MODE ? p3.y : p3.x;
        int s7 = MODE ? p3.w : p3.z;
        uint4 u0 = tab[s0 * 8 + c];
        uint4 u1 = tab[s1 * 8 + c];
        uint4 u2 = tab[s2 * 8 + c];
        uint4 u3 = tab[s3 * 8 + c];
        uint4 u4 = tab[s4 * 8 + c];
        uint4 u5 = tab[s5 * 8 + c];
        uint4 u6 = tab[s6 * 8 + c];
        uint4 u7 = tab[s7 * 8 + c];
        acc8h(A, B, u0);
        acc8h(A, B, u1);
        acc8h(A, B, u2);
        acc8h(A, B, u3);
        acc8h(A, B, u4);
        acc8h(A, B, u5);
        acc8h(A, B, u6);
        acc8h(A, B, u7);
    }
    __half2 q0 = __floats2half2_rn(A.x, A.y);
    __half2 q1 = __floats2half2_rn(A.z, A.w);
    __half2 q2 = __floats2half2_rn(B.x, B.y);
    __half2 q3 = __floats2half2_rn(B.z, B.w);
    ((uint4*)g_zh)[n * 8 + c] = make_uint4(*(unsigned*)&q0, *(unsigned*)&q1,
                                           *(unsigned*)&q2, *(unsigned*)&q3);
}

// ---------------------------------------------------------------------------
// MLP via tensor cores (HMMA m16n8k16, fp16 in / fp32 accum):
//   h = relu(z@W1+b1)@W2 + b2.
// 128 threads (4 warps), 128 nodes/block. Warp owns 32 rows x 64 cols.
// GEMM1 C-regs -> relu -> fp16 A-fragments for GEMM2 IN REGISTERS.
// LAST layer: fused pool+head.
// ---------------------------------------------------------------------------
#define WS 72   // padded row stride in halves (144B -> conflict-free ldmatrix)

#define LDSM_X4(r0, r1, r2, r3, a) \
    asm volatile("ldmatrix.sync.aligned.m8n8.x4.shared.b16 {%0,%1,%2,%3}, [%4];" \
                 : "=r"(r0), "=r"(r1), "=r"(r2), "=r"(r3) : "r"(a))
#define LDSM_X4T(r0, r1, r2, r3, a) \
    asm volatile("ldmatrix.sync.aligned.m8n8.x4.trans.shared.b16 {%0,%1,%2,%3}, [%4];" \
                 : "=r"(r0), "=r"(r1), "=r"(r2), "=r"(r3) : "r"(a))
#define MMA16816(c, a, b) \
    asm volatile("mma.sync.aligned.m16n8k16.row.col.f32.f16.f16.f32 " \
                 "{%0,%1,%2,%3}, {%4,%5,%6,%7}, {%8,%9}, {%0,%1,%2,%3};" \
                 : "+f"((c)[0]), "+f"((c)[1]), "+f"((c)[2]), "+f"((c)[3]) \
                 : "r"((a)[0]), "r"((a)[1]), "r"((a)[2]), "r"((a)[3]), \
                   "r"((b)[0]), "r"((b)[1]))

__global__ void __launch_bounds__(128)
mlp_kernel(const float* __restrict__ b1, const float* __restrict__ b2,
           int layer, int last,
           const int* __restrict__ gids, const float* __restrict__ Wr,
           float* __restrict__ out) {
    __shared__ __align__(16) __half sW1[HID * WS];
    __shared__ __align__(16) __half sW2[HID * WS];
    __shared__ __align__(16) __half sZ[NPB * WS];

    const int tid  = threadIdx.x;
    const int lane = tid & 31;
    const int w    = tid >> 5;
    const int nbase = blockIdx.x * NPB;

    // ---- stage fp16 weights (padded rows) ----
    {
        const uint4* w1g = (const uint4*)(g_w1h + layer * HID * HID);
        const uint4* w2g = (const uint4*)(g_w2h + layer * HID * HID);
#pragma unroll
        for (int idx = tid; idx < 512; idx += 128) {
            int r = idx >> 3, c = idx & 7;
            *(uint4*)&sW1[r * WS + c * 8] = w1g[idx];
            *(uint4*)&sW2[r * WS + c * 8] = w2g[idx];
        }
    }
    // ---- stage z tile (one 128B row per thread) ----
    {
        int n = nbase + tid;
        if (n < N_NODES) {
            const uint4* zr = (const uint4*)(g_zh + n * HID);
#pragma unroll
            for (int q = 0; q < 8; q++)
                *(uint4*)&sZ[tid * WS + q * 8] = zr[q];
        } else {
            uint4 zz = make_uint4(0u, 0u, 0u, 0u);
#pragma unroll
            for (int q = 0; q < 8; q++)
                *(uint4*)&sZ[tid * WS + q * 8] = zz;
        }
    }
    __syncthreads();

    const float* b1g = b1 + layer * HID;
    const float* b2g = b2 + layer * HID;

    float acc[2][8][4];
    unsigned ya[2][8][2];   // relu(GEMM1) as fp16 A-fragments

    // ================= GEMM 1: Y = relu(Z @ W1 + b1) =================
#pragma unroll
    for (int nt = 0; nt < 8; nt++) {
        int col = nt * 8 + (lane & 3) * 2;
        float v0 = __ldg(b1g + col), v1 = __ldg(b1g + col + 1);
#pragma unroll
        for (int mt = 0; mt < 2; mt++) {
            acc[mt][nt][0] = v0; acc[mt][nt][1] = v1;
            acc[mt][nt][2] = v0; acc[mt][nt][3] = v1;
        }
    }
#pragma unroll
    for (int ks = 0; ks < 4; ks++) {
        unsigned a[2][4], bf[8][2];
#pragma unroll
        for (int mt = 0; mt < 2; mt++) {
            int row = 32 * w + mt * 16 + (lane & 15);
            int ch  = ks * 16 + ((lane >> 4) << 3);
            LDSM_X4(a[mt][0], a[mt][1], a[mt][2], a[mt][3],
                    su32(&sZ[row * WS + ch]));
        }
#pragma unroll
        for (int ntp = 0; ntp < 4; ntp++) {
            int kr = ks * 16 + (((lane >> 3) & 1) << 3) + (lane & 7);
            int nc = ntp * 16 + ((lane >> 4) << 3);
            LDSM_X4T(bf[2 * ntp][0], bf[2 * ntp][1],
                     bf[2 * ntp + 1][0], bf[2 * ntp + 1][1],
                     su32(&sW1[kr * WS + nc]));
        }
#pragma unroll
        for (int mt = 0; mt < 2; mt++)
#pragma unroll
            for (int nt = 0; nt < 8; nt++)
                MMA16816(acc[mt][nt], a[mt], bf[nt]);
    }
    // relu + pack fp16 (C layout == A layout)
#pragma unroll
    for (int mt = 0; mt < 2; mt++)
#pragma unroll
        for (int nt = 0; nt < 8; nt++) {
            __half2 y0 = __floats2half2_rn(fmaxf(acc[mt][nt][0], 0.f),
                                           fmaxf(acc[mt][nt][1], 0.f));
            __half2 y1 = __floats2half2_rn(fmaxf(acc[mt][nt][2], 0.f),
                                           fmaxf(acc[mt][nt][3], 0.f));
            ya[mt][nt][0] = *(unsigned*)&y0;
            ya[mt][nt][1] = *(unsigned*)&y1;
        }

    // ================= GEMM 2: H = Y @ W2 + b2 =================
#pragma unroll
    for (int nt = 0; nt < 8; nt++) {
        int col = nt * 8 + (lane & 3) * 2;
        float v0 = __ldg(b2g + col), v1 = __ldg(b2g + col + 1);
#pragma unroll
        for (int mt = 0; mt < 2; mt++) {
            acc[mt][nt][0] = v0; acc[mt][nt][1] = v1;
            acc[mt][nt][2] = v0; acc[mt][nt][3] = v1;
        }
    }
#pragma unroll
    for (int kt = 0; kt < 4; kt++) {
        unsigned bf[8][2];
#pragma unroll
        for (int ntp = 0; ntp < 4; ntp++) {
            int kr = kt * 16 + (((lane >> 3) & 1) << 3) + (lane & 7);
            int nc = ntp * 16 + ((lane >> 4) << 3);
            LDSM_X4T(bf[2 * ntp][0], bf[2 * ntp][1],
                     bf[2 * ntp + 1][0], bf[2 * ntp + 1][1],
                     su32(&sW2[kr * WS + nc]));
        }
#pragma unroll
        for (int mt = 0; mt < 2; mt++) {
            unsigned a2[4] = { ya[mt][2 * kt][0],     ya[mt][2 * kt][1],
                               ya[mt][2 * kt + 1][0], ya[mt][2 * kt + 1][1] };
#pragma unroll
            for (int nt = 0; nt < 8; nt++)
                MMA16816(acc[mt][nt], a2, bf[nt]);
        }
    }

    if (!last) {
        // store h fp16: thread owns (row0, row0+8) x col pairs per tile
#pragma unroll
        for (int mt = 0; mt < 2; mt++) {
            int row0 = nbase + 32 * w + mt * 16 + (lane >> 2);
#pragma unroll
            for (int nt = 0; nt < 8; nt++) {
                int col = nt * 8 + (lane & 3) * 2;
                if (row0 < N_NODES) {
                    __half2 v = __floats2half2_rn(acc[mt][nt][0], acc[mt][nt][1]);
                    *(__half2*)&g_hh[row0 * HID + col] = v;
                }
                if (row0 + 8 < N_NODES) {
                    __half2 v = __floats2half2_rn(acc[mt][nt][2], acc[mt][nt][3]);
                    *(__half2*)&g_hh[(row0 + 8) * HID + col] = v;
                }
            }
        }
    } else {
        // fused pool + head: dot rows with Wr, reduce over 4 col-lanes
#pragma unroll
        for (int mt = 0; mt < 2; mt++) {
            float d0 = 0.f, d1 = 0.f;
#pragma unroll
            for (int nt = 0; nt < 8; nt++) {
                int col = nt * 8 + (lane & 3) * 2;
                float wr0 = __ldg(Wr + col), wr1 = __ldg(Wr + col + 1);
                d0 = fmaf(acc[mt][nt][0], wr0, fmaf(acc[mt][nt][1], wr1, d0));
                d1 = fmaf(acc[mt][nt][2], wr0, fmaf(acc[mt][nt][3], wr1, d1));
            }
            d0 += __shfl_xor_sync(0xffffffffu, d0, 1);
            d0 += __shfl_xor_sync(0xffffffffu, d0, 2);
            d1 += __shfl_xor_sync(0xffffffffu, d1, 1);
            d1 += __shfl_xor_sync(0xffffffffu, d1, 2);
            if ((lane & 3) == 0) {
                int row0 = nbase + 32 * w + mt * 16 + (lane >> 2);
                if (row0 < N_NODES)
                    atomicAdd(out + __ldg(gids + row0), d0);
                if (row0 + 8 < N_NODES)
                    atomicAdd(out + __ldg(gids + row0 + 8), d1);
            }
        }
    }
}

// ---------------------------------------------------------------------------
extern "C" void kernel_launch(void* const* d_in, const int* in_sizes, int n_in,
                              void* d_out, int out_size) {
    const int*   feats = (const int*)d_in[0];
    const int*   src   = (const int*)d_in[1];
    const int*   dst   = (const int*)d_in[2];
    const int*   gids  = (const int*)d_in[3];
    const float* emb   = (const float*)d_in[4];
    const float* W1    = (const float*)d_in[5];
    const float* b1    = (const float*)d_in[6];
    const float* W2    = (const float*)d_in[7];
    const float* b2    = (const float*)d_in[8];
    const float* Wr    = (const float*)d_in[9];
    float* out = (float*)d_out;

    // CSR build (padded rows) + prep — 3 kernels
    setup_kernel<<<(CSR_CAP / 4 + 255) / 256, 256>>>(dst, feats, emb, W1, W2, out);
    scan_kernel<<<SCAN_BLKS, 1024>>>();
    scatter_kernel<<<(N_EDGES / 4 + 255) / 256, 256>>>(src, dst);

    // 3 GIN layers
    const int ablk = (N_NODES * 8 + 255) / 256;
    const int mblk = (N_NODES + NPB - 1) / NPB;

    agg_kernel_t<1><<<ablk, 256>>>();
    mlp_kernel<<<mblk, 128>>>(b1, b2, 0, 0, gids, Wr, out);
    agg_kernel_t<0><<<ablk, 256>>>();
    mlp_kernel<<<mblk, 128>>>(b1, b2, 1, 0, gids, Wr, out);
    agg_kernel_t<0><<<ablk, 256>>>();
    mlp_kernel<<<mblk, 128>>>(b1, b2, 2, 1, gids, Wr, out);
}

// round 15
// speedup vs baseline: 1.1494x; 1.0323x over previous
#include <cuda_runtime.h>
#include <cuda_fp16.h>

#define N_NODES  50000
#define N_EDGES  800000
#define N_GRAPHS 128
#define HID      64
#define VOCAB    100
#define LAYERS   3
#define NPB      128                          // nodes per block in mlp kernel
#define CSR_CAP  (N_EDGES + 7 * N_NODES)      // padded CSR capacity
#define SCAN_BLKS ((N_NODES + 1023) / 1024)   // 49

// Scratch (__device__ globals — allocation-free rule).
// Row N_NODES of g_hh and row VOCAB of g_embh are permanent ZERO rows
// (never written): padded-CSR dummy gather targets.
// g_deg invariant: zero at entry (static init; scan_kernel re-zeros).
__device__ __half g_hh[(N_NODES + 1) * HID];   // fp16 inter-layer h (128B/row)
__device__ __half g_zh[N_NODES * HID];         // fp16 aggregated z (128B/row)
__device__ __half g_embh[(VOCAB + 1) * HID];   // fp16 embedding (L1-resident)
__device__ __half g_w1h[LAYERS * HID * HID];   // fp16 W1
__device__ __half g_w2h[LAYERS * HID * HID];   // fp16 W2
__device__ int    g_feats_pad[N_NODES + 1];
__device__ int    g_deg[N_NODES];
__device__ int    g_rowptr[N_NODES + 1];
__device__ int    g_pos[N_NODES];
__device__ int    g_blk_agg[SCAN_BLKS];
__device__ int2   g_csr[CSR_CAP];              // (src, feat[src]) per edge

__device__ __forceinline__ unsigned su32(const void* p) {
    return (unsigned)__cvta_generic_to_shared(p);
}

// ---------------------------------------------------------------------------
// Setup: CSR pad-fill + degree hist + fp16 emb/W1/W2 + padded feats + zeroing
// ---------------------------------------------------------------------------
__global__ void setup_kernel(const int* __restrict__ dst,
                             const int* __restrict__ feats,
                             const float* __restrict__ emb,
                             const float* __restrict__ W1,
                             const float* __restrict__ W2,
                             float* __restrict__ out) {
    int i = blockIdx.x * blockDim.x + threadIdx.x;
    if (i * 4 < CSR_CAP) {
        int4 pad = make_int4(N_NODES, VOCAB, N_NODES, VOCAB);
        ((int4*)g_csr)[2 * i]     = pad;
        ((int4*)g_csr)[2 * i + 1] = pad;
    }
    if (i * 4 < N_EDGES) {
        int4 d = ((const int4*)dst)[i];
        atomicAdd(&g_deg[d.x], 1);
        atomicAdd(&g_deg[d.y], 1);
        atomicAdd(&g_deg[d.z], 1);
        atomicAdd(&g_deg[d.w], 1);
    }
    if (i < (VOCAB + 1) * HID)
        g_embh[i] = __float2half_rn((i < VOCAB * HID) ? emb[i] : 0.f);
    if (i < LAYERS * HID * HID) {
        g_w1h[i] = __float2half_rn(W1[i]);
        g_w2h[i] = __float2half_rn(W2[i]);
    }
    if (i < N_NODES)       g_feats_pad[i] = __ldg(feats + i);
    else if (i == N_NODES) g_feats_pad[i] = VOCAB;
    if (i < SCAN_BLKS) g_blk_agg[i] = 0;
    if (i < N_GRAPHS)  out[i] = 0.f;
}

// ---------------------------------------------------------------------------
// Single-pass scan of PADDED degrees (x8) -> rowptr + pos; re-zeros g_deg.
// 49 blocks all resident in one wave -> spin on predecessor aggregates safe.
// ---------------------------------------------------------------------------
__global__ void __launch_bounds__(1024) scan_kernel() {
    __shared__ int warp_sums[32];
    __shared__ int block_prefix;
    const int t = threadIdx.x, b = blockIdx.x;
    const int lane = t & 31, warp = t >> 5;
    if (t == 0) block_prefix = 0;

    int i = b * 1024 + t;
    int d = 0;
    if (i < N_NODES) {
        d = (g_deg[i] + 7) & ~7;
        g_deg[i] = 0;
    }

    int incl = d;
#pragma unroll
    for (int off = 1; off < 32; off <<= 1) {
        int u = __shfl_up_sync(0xffffffffu, incl, off);
        if (lane >= off) incl += u;
    }
    if (lane == 31) warp_sums[warp] = incl;
    __syncthreads();

    if (warp == 0) {
        int v = warp_sums[lane];
        int w = v;
#pragma unroll
        for (int off = 1; off < 32; off <<= 1) {
            int u = __shfl_up_sync(0xffffffffu, w, off);
            if (lane >= off) w += u;
        }
        warp_sums[lane] = w;
    }
    __syncthreads();

    int wexcl = (warp > 0) ? warp_sums[warp - 1] : 0;
    int excl  = wexcl + incl - d;
    int block_total = warp_sums[31];

    if (t == 0)
        *(volatile int*)&g_blk_agg[b] = block_total + 1;

    if (t < b) {
        int v;
        do { v = *(volatile int*)&g_blk_agg[t]; } while (v == 0);
        atomicAdd(&block_prefix, v - 1);
    }
    __syncthreads();

    int r = block_prefix + excl;
    if (i < N_NODES) {
        g_rowptr[i] = r;
        g_pos[i]    = r;
    }
    if (b == SCAN_BLKS - 1 && t == 1023)
        g_rowptr[N_NODES] = block_prefix + excl + d;
}

// ---------------------------------------------------------------------------
// Scatter: one 8B (src, feat) store per edge. 8 edges/thread for deeper
// atomic-latency pipelining (scatter is ATOMG-latency-bound).
// ---------------------------------------------------------------------------
__global__ void scatter_kernel(const int* __restrict__ src,
                               const int* __restrict__ dst) {
    int i = blockIdx.x * blockDim.x + threadIdx.x;
    if (i * 8 >= N_EDGES) return;
    int4 s0 = ((const int4*)src)[2 * i];
    int4 s1 = ((const int4*)src)[2 * i + 1];
    int4 d0 = ((const int4*)dst)[2 * i];
    int4 d1 = ((const int4*)dst)[2 * i + 1];
    int f0 = __ldg(&g_feats_pad[s0.x]);
    int f1 = __ldg(&g_feats_pad[s0.y]);
    int f2 = __ldg(&g_feats_pad[s0.z]);
    int f3 = __ldg(&g_feats_pad[s0.w]);
    int f4 = __ldg(&g_feats_pad[s1.x]);
    int f5 = __ldg(&g_feats_pad[s1.y]);
    int f6 = __ldg(&g_feats_pad[s1.z]);
    int f7 = __ldg(&g_feats_pad[s1.w]);
    int p0 = atomicAdd(&g_pos[d0.x], 1);
    int p1 = atomicAdd(&g_pos[d0.y], 1);
    int p2 = atomicAdd(&g_pos[d0.z], 1);
    int p3 = atomicAdd(&g_pos[d0.w], 1);
    int p4 = atomicAdd(&g_pos[d1.x], 1);
    int p5 = atomicAdd(&g_pos[d1.y], 1);
    int p6 = atomicAdd(&g_pos[d1.z], 1);
    int p7 = atomicAdd(&g_pos[d1.w], 1);
    g_csr[p0] = make_int2(s0.x, f0);
    g_csr[p1] = make_int2(s0.y, f1);
    g_csr[p2] = make_int2(s0.z, f2);
    g_csr[p3] = make_int2(s0.w, f3);
    g_csr[p4] = make_int2(s1.x, f4);
    g_csr[p5] = make_int2(s1.y, f5);
    g_csr[p6] = make_int2(s1.z, f6);
    g_csr[p7] = make_int2(s1.w, f7);
}

// ---------------------------------------------------------------------------
// Unified aggregation, TEMPLATED on MODE.
//   MODE=1: z[n] = embh[feat[n]] + sum embh[csr[e].y]
//   MODE=0: z[n] = hh[n]        + sum hh[csr[e].x]
// 8 threads/node, one uint4 (8 halves) each, PAIRWISE fp16 pre-reduction
// (one extra fp16 rounding, ~storage-level) then fp32 accumulate; fp16 z out.
// Padded CSR rows (x8) -> no remainder.
// ---------------------------------------------------------------------------
__device__ __forceinline__ void acc8h(float4& A, float4& B, uint4 u) {
    float2 f;
    f = __half22float2(*(const __half2*)&u.x); A.x += f.x; A.y += f.y;
    f = __half22float2(*(const __half2*)&u.y); A.z += f.x; A.w += f.y;
    f = __half22float2(*(const __half2*)&u.z); B.x += f.x; B.y += f.y;
    f = __half22float2(*(const __half2*)&u.w); B.z += f.x; B.w += f.y;
}

__device__ __forceinline__ uint4 hadd4(uint4 a, uint4 b) {
    uint4 r;
    *(__half2*)&r.x = __hadd2(*(const __half2*)&a.x, *(const __half2*)&b.x);
    *(__half2*)&r.y = __hadd2(*(const __half2*)&a.y, *(const __half2*)&b.y);
    *(__half2*)&r.z = __hadd2(*(const __half2*)&a.z, *(const __half2*)&b.z);
    *(__half2*)&r.w = __hadd2(*(const __half2*)&a.w, *(const __half2*)&b.w);
    return r;
}

template <int MODE>
__global__ void __launch_bounds__(256)
agg_kernel_t() {
    int i = blockIdx.x * blockDim.x + threadIdx.x;
    if (i >= N_NODES * 8) return;
    int n = i >> 3;
    int c = i & 7;
    const uint4* tab = MODE ? (const uint4*)g_embh : (const uint4*)g_hh;

    float4 A = {0.f, 0.f, 0.f, 0.f}, B = {0.f, 0.f, 0.f, 0.f};
    int self = MODE ? __ldg(&g_feats_pad[n]) : n;
    acc8h(A, B, tab[self * 8 + c]);

    int e   = __ldg(&g_rowptr[n]);
    int end = __ldg(&g_rowptr[n + 1]);
    for (; e < end; e += 8) {
        int4 p0 = *(const int4*)&g_csr[e];       // (s,f, s,f) edges e,e+1
        int4 p1 = *(const int4*)&g_csr[e + 2];
        int4 p2 = *(const int4*)&g_csr[e + 4];
        int4 p3 = *(const int4*)&g_csr[e + 6];
        int s0 = MODE ? p0.y : p0.x;
        int s1 = MODE ? p0.w : p0.z;
        int s2 = MODE ? p1.y : p1.x;
        int s3 = MODE ? p1.w : p1.z;
        int s4 = MODE ? p2.y : p2.x;
        int s5 = MODE ? p2.w : p2.z;
        int s6 = MODE ? p3.y : p3.x;
        int s7 = MODE ? p3.w : p3.z;
        uint4 u0 = tab[s0 * 8 + c];
        uint4 u1 = tab[s1 * 8 + c];
        uint4 u2 = tab[s2 * 8 + c];
        uint4 u3 = tab[s3 * 8 + c];
        uint4 u4 = tab[s4 * 8 + c];
        uint4 u5 = tab[s5 * 8 + c];
        uint4 u6 = tab[s6 * 8 + c];
        uint4 u7 = tab[s7 * 8 + c];
        // pairwise fp16 pre-reduction (one extra rounding), then fp32 accum
        uint4 v0 = hadd4(u0, u1);
        uint4 v1 = hadd4(u2, u3);
        uint4 v2 = hadd4(u4, u5);
        uint4 v3 = hadd4(u6, u7);
        acc8h(A, B, v0);
        acc8h(A, B, v1);
        acc8h(A, B, v2);
        acc8h(A, B, v3);
    }
    __half2 q0 = __floats2half2_rn(A.x, A.y);
    __half2 q1 = __floats2half2_rn(A.z, A.w);
    __half2 q2 = __floats2half2_rn(B.x, B.y);
    __half2 q3 = __floats2half2_rn(B.z, B.w);
    ((uint4*)g_zh)[n * 8 + c] = make_uint4(*(unsigned*)&q0, *(unsigned*)&q1,
                                           *(unsigned*)&q2, *(unsigned*)&q3);
}

// ---------------------------------------------------------------------------
// MLP via tensor cores (HMMA m16n8k16, fp16 in / fp32 accum):
//   h = relu(z@W1+b1)@W2 + b2.
// 128 threads (4 warps), 128 nodes/block. Warp owns 32 rows x 64 cols.
// GEMM1 C-regs -> relu -> fp16 A-fragments for GEMM2 IN REGISTERS.
// LAST layer: fused pool+head.
// ---------------------------------------------------------------------------
#define WS 72   // padded row stride in halves (144B -> conflict-free ldmatrix)

#define LDSM_X4(r0, r1, r2, r3, a) \
    asm volatile("ldmatrix.sync.aligned.m8n8.x4.shared.b16 {%0,%1,%2,%3}, [%4];" \
                 : "=r"(r0), "=r"(r1), "=r"(r2), "=r"(r3) : "r"(a))
#define LDSM_X4T(r0, r1, r2, r3, a) \
    asm volatile("ldmatrix.sync.aligned.m8n8.x4.trans.shared.b16 {%0,%1,%2,%3}, [%4];" \
                 : "=r"(r0), "=r"(r1), "=r"(r2), "=r"(r3) : "r"(a))
#define MMA16816(c, a, b) \
    asm volatile("mma.sync.aligned.m16n8k16.row.col.f32.f16.f16.f32 " \
                 "{%0,%1,%2,%3}, {%4,%5,%6,%7}, {%8,%9}, {%0,%1,%2,%3};" \
                 : "+f"((c)[0]), "+f"((c)[1]), "+f"((c)[2]), "+f"((c)[3]) \
                 : "r"((a)[0]), "r"((a)[1]), "r"((a)[2]), "r"((a)[3]), \
                   "r"((b)[0]), "r"((b)[1]))

__global__ void __launch_bounds__(128)
mlp_kernel(const float* __restrict__ b1, const float* __restrict__ b2,
           int layer, int last,
           const int* __restrict__ gids, const float* __restrict__ Wr,
           float* __restrict__ out) {
    __shared__ __align__(16) __half sW1[HID * WS];
    __shared__ __align__(16) __half sW2[HID * WS];
    __shared__ __align__(16) __half sZ[NPB * WS];

    const int tid  = threadIdx.x;
    const int lane = tid & 31;
    const int w    = tid >> 5;
    const int nbase = blockIdx.x * NPB;

    // ---- stage fp16 weights (padded rows) ----
    {
        const uint4* w1g = (const uint4*)(g_w1h + layer * HID * HID);
        const uint4* w2g = (const uint4*)(g_w2h + layer * HID * HID);
#pragma unroll
        for (int idx = tid; idx < 512; idx += 128) {
            int r = idx >> 3, c = idx & 7;
            *(uint4*)&sW1[r * WS + c * 8] = w1g[idx];
            *(uint4*)&sW2[r * WS + c * 8] = w2g[idx];
        }
    }
    // ---- stage z tile (one 128B row per thread) ----
    {
        int n = nbase + tid;
        if (n < N_NODES) {
            const uint4* zr = (const uint4*)(g_zh + n * HID);
#pragma unroll
            for (int q = 0; q < 8; q++)
                *(uint4*)&sZ[tid * WS + q * 8] = zr[q];
        } else {
            uint4 zz = make_uint4(0u, 0u, 0u, 0u);
#pragma unroll
            for (int q = 0; q < 8; q++)
                *(uint4*)&sZ[tid * WS + q * 8] = zz;
        }
    }
    __syncthreads();

    const float* b1g = b1 + layer * HID;
    const float* b2g = b2 + layer * HID;

    float acc[2][8][4];
    unsigned ya[2][8][2];   // relu(GEMM1) as fp16 A-fragments

    // ================= GEMM 1: Y = relu(Z @ W1 + b1) =================
#pragma unroll
    for (int nt = 0; nt < 8; nt++) {
        int col = nt * 8 + (lane & 3) * 2;
        float v0 = __ldg(b1g + col), v1 = __ldg(b1g + col + 1);
#pragma unroll
        for (int mt = 0; mt < 2; mt++) {
            acc[mt][nt][0] = v0; acc[mt][nt][1] = v1;
            acc[mt][nt][2] = v0; acc[mt][nt][3] = v1;
        }
    }
#pragma unroll
    for (int ks = 0; ks < 4; ks++) {
        unsigned a[2][4], bf[8][2];
#pragma unroll
        for (int mt = 0; mt < 2; mt++) {
            int row = 32 * w + mt * 16 + (lane & 15);
            int ch  = ks * 16 + ((lane >> 4) << 3);
            LDSM_X4(a[mt][0], a[mt][1], a[mt][2], a[mt][3],
                    su32(&sZ[row * WS + ch]));
        }
#pragma unroll
        for (int ntp = 0; ntp < 4; ntp++) {
            int kr = ks * 16 + (((lane >> 3) & 1) << 3) + (lane & 7);
            int nc = ntp * 16 + ((lane >> 4) << 3);
            LDSM_X4T(bf[2 * ntp][0], bf[2 * ntp][1],
                     bf[2 * ntp + 1][0], bf[2 * ntp + 1][1],
                     su32(&sW1[kr * WS + nc]));
        }
#pragma unroll
        for (int mt = 0; mt < 2; mt++)
#pragma unroll
            for (int nt = 0; nt < 8; nt++)
                MMA16816(acc[mt][nt], a[mt], bf[nt]);
    }
    // relu + pack fp16 (C layout == A layout)
#pragma unroll
    for (int mt = 0; mt < 2; mt++)
#pragma unroll
        for (int nt = 0; nt < 8; nt++) {
            __half2 y0 = __floats2half2_rn(fmaxf(acc[mt][nt][0], 0.f),
                                           fmaxf(acc[mt][nt][1], 0.f));
            __half2 y1 = __floats2half2_rn(fmaxf(acc[mt][nt][2], 0.f),
                                           fmaxf(acc[mt][nt][3], 0.f));
            ya[mt][nt][0] = *(unsigned*)&y0;
            ya[mt][nt][1] = *(unsigned*)&y1;
        }

    // ================= GEMM 2: H = Y @ W2 + b2 =================
#pragma unroll
    for (int nt = 0; nt < 8; nt++) {
        int col = nt * 8 + (lane & 3) * 2;
        float v0 = __ldg(b2g + col), v1 = __ldg(b2g + col + 1);
#pragma unroll
        for (int mt = 0; mt < 2; mt++) {
            acc[mt][nt][0] = v0; acc[mt][nt][1] = v1;
            acc[mt][nt][2] = v0; acc[mt][nt][3] = v1;
        }
    }
#pragma unroll
    for (int kt = 0; kt < 4; kt++) {
        unsigned bf[8][2];
#pragma unroll
        for (int ntp = 0; ntp < 4; ntp++) {
            int kr = kt * 16 + (((lane >> 3) & 1) << 3) + (lane & 7);
            int nc = ntp * 16 + ((lane >> 4) << 3);
            LDSM_X4T(bf[2 * ntp][0], bf[2 * ntp][1],
                     bf[2 * ntp + 1][0], bf[2 * ntp + 1][1],
                     su32(&sW2[kr * WS + nc]));
        }
#pragma unroll
        for (int mt = 0; mt < 2; mt++) {
            unsigned a2[4] = { ya[mt][2 * kt][0],     ya[mt][2 * kt][1],
                               ya[mt][2 * kt + 1][0], ya[mt][2 * kt + 1][1] };
#pragma unroll
            for (int nt = 0; nt < 8; nt++)
                MMA16816(acc[mt][nt], a2, bf[nt]);
        }
    }

    if (!last) {
        // store h fp16: thread owns (row0, row0+8) x col pairs per tile
#pragma unroll
        for (int mt = 0; mt < 2; mt++) {
            int row0 = nbase + 32 * w + mt * 16 + (lane >> 2);
#pragma unroll
            for (int nt = 0; nt < 8; nt++) {
                int col = nt * 8 + (lane & 3) * 2;
                if (row0 < N_NODES) {
                    __half2 v = __floats2half2_rn(acc[mt][nt][0], acc[mt][nt][1]);
                    *(__half2*)&g_hh[row0 * HID + col] = v;
                }
                if (row0 + 8 < N_NODES) {
                    __half2 v = __floats2half2_rn(acc[mt][nt][2], acc[mt][nt][3]);
                    *(__half2*)&g_hh[(row0 + 8) * HID + col] = v;
                }
            }
        }
    } else {
        // fused pool + head: dot rows with Wr, reduce over 4 col-lanes
#pragma unroll
        for (int mt = 0; mt < 2; mt++) {
            float d0 = 0.f, d1 = 0.f;
#pragma unroll
            for (int nt = 0; nt < 8; nt++) {
                int col = nt * 8 + (lane & 3) * 2;
                float wr0 = __ldg(Wr + col), wr1 = __ldg(Wr + col + 1);
                d0 = fmaf(acc[mt][nt][0], wr0, fmaf(acc[mt][nt][1], wr1, d0));
                d1 = fmaf(acc[mt][nt][2], wr0, fmaf(acc[mt][nt][3], wr1, d1));
            }
            d0 += __shfl_xor_sync(0xffffffffu, d0, 1);
            d0 += __shfl_xor_sync(0xffffffffu, d0, 2);
            d1 += __shfl_xor_sync(0xffffffffu, d1, 1);
            d1 += __shfl_xor_sync(0xffffffffu, d1, 2);
            if ((lane & 3) == 0) {
                int row0 = nbase + 32 * w + mt * 16 + (lane >> 2);
                if (row0 < N_NODES)
                    atomicAdd(out + __ldg(gids + row0), d0);
                if (row0 + 8 < N_NODES)
                    atomicAdd(out + __ldg(gids + row0 + 8), d1);
            }
        }
    }
}

// ---------------------------------------------------------------------------
extern "C" void kernel_launch(void* const* d_in, const int* in_sizes, int n_in,
                              void* d_out, int out_size) {
    const int*   feats = (const int*)d_in[0];
    const int*   src   = (const int*)d_in[1];
    const int*   dst   = (const int*)d_in[2];
    const int*   gids  = (const int*)d_in[3];
    const float* emb   = (const float*)d_in[4];
    const float* W1    = (const float*)d_in[5];
    const float* b1    = (const float*)d_in[6];
    const float* W2    = (const float*)d_in[7];
    const float* b2    = (const float*)d_in[8];
    const float* Wr    = (const float*)d_in[9];
    float* out = (float*)d_out;

    // CSR build (padded rows) + prep — 3 kernels
    setup_kernel<<<(CSR_CAP / 4 + 255) / 256, 256>>>(dst, feats, emb, W1, W2, out);
    scan_kernel<<<SCAN_BLKS, 1024>>>();
    scatter_kernel<<<(N_EDGES / 8 + 255) / 256, 256>>>(src, dst);

    // 3 GIN layers
    const int ablk = (N_NODES * 8 + 255) / 256;
    const int mblk = (N_NODES + NPB - 1) / NPB;

    agg_kernel_t<1><<<ablk, 256>>>();
    mlp_kernel<<<mblk, 128>>>(b1, b2, 0, 0, gids, Wr, out);
    agg_kernel_t<0><<<ablk, 256>>>();
    mlp_kernel<<<mblk, 128>>>(b1, b2, 1, 0, gids, Wr, out);
    agg_kernel_t<0><<<ablk, 256>>>();
    mlp_kernel<<<mblk, 128>>>(b1, b2, 2, 1, gids, Wr, out);
}

// round 16
// speedup vs baseline: 1.2486x; 1.0863x over previous
#include <cuda_runtime.h>
#include <cuda_fp16.h>

#define N_NODES  50000
#define N_EDGES  800000
#define N_GRAPHS 128
#define HID      64
#define VOCAB    100
#define LAYERS   3
#define NPB      128                          // nodes per block in mlp kernel
#define CSR_CAP  (N_EDGES + 7 * N_NODES)      // padded CSR capacity
#define SCAN_BLKS ((N_NODES + 1023) / 1024)   // 49

// Scratch (__device__ globals — allocation-free rule).
// Row N_NODES of g_hh and row VOCAB of g_embh are permanent ZERO rows
// (never written): padded-CSR dummy gather targets.
// g_deg invariant: zero at entry (static init; scan_kernel re-zeros).
__device__ __half g_hh[(N_NODES + 1) * HID];   // fp16 inter-layer h (128B/row)
__device__ __half g_zh[N_NODES * HID];         // fp16 aggregated z (128B/row)
__device__ __half g_embh[(VOCAB + 1) * HID];   // fp16 embedding (L1-resident)
__device__ __half g_w1h[LAYERS * HID * HID];   // fp16 W1
__device__ __half g_w2h[LAYERS * HID * HID];   // fp16 W2
__device__ int    g_feats_pad[N_NODES + 1];
__device__ int    g_deg[N_NODES];
__device__ int    g_rowptr[N_NODES + 1];
__device__ int    g_pos[N_NODES];
__device__ int    g_blk_agg[SCAN_BLKS];
__device__ int2   g_csr[CSR_CAP];              // (src, feat[src]) per edge

__device__ __forceinline__ unsigned su32(const void* p) {
    return (unsigned)__cvta_generic_to_shared(p);
}

// PDL protocol: every kernel syncs on its predecessor BEFORE triggering, so
// when any block of kernel K runs, all kernels ≥2 before K are complete.
// Pre-sync code may therefore read: harness inputs + outputs of kernels ≥2
// back. Outputs of the immediate predecessor only after PDL_SYNC.
#define PDL_SYNC()    cudaGridDependencySynchronize()
#define PDL_TRIGGER() cudaTriggerProgrammaticLaunchCompletion()

// ---------------------------------------------------------------------------
// Setup: CSR pad-fill + degree hist + fp16 emb/W1/W2 + padded feats + zeroing
// ---------------------------------------------------------------------------
__global__ void setup_kernel(const int* __restrict__ dst,
                             const int* __restrict__ feats,
                             const float* __restrict__ emb,
                             const float* __restrict__ W1,
                             const float* __restrict__ W2,
                             float* __restrict__ out) {
    PDL_SYNC();
    PDL_TRIGGER();
    int i = blockIdx.x * blockDim.x + threadIdx.x;
    if (i * 4 < CSR_CAP) {
        int4 pad = make_int4(N_NODES, VOCAB, N_NODES, VOCAB);
        ((int4*)g_csr)[2 * i]     = pad;
        ((int4*)g_csr)[2 * i + 1] = pad;
    }
    if (i * 4 < N_EDGES) {
        int4 d = ((const int4*)dst)[i];
        atomicAdd(&g_deg[d.x], 1);
        atomicAdd(&g_deg[d.y], 1);
        atomicAdd(&g_deg[d.z], 1);
        atomicAdd(&g_deg[d.w], 1);
    }
    if (i < (VOCAB + 1) * HID)
        g_embh[i] = __float2half_rn((i < VOCAB * HID) ? emb[i] : 0.f);
    if (i < LAYERS * HID * HID) {
        g_w1h[i] = __float2half_rn(W1[i]);
        g_w2h[i] = __float2half_rn(W2[i]);
    }
    if (i < N_NODES)       g_feats_pad[i] = __ldg(feats + i);
    else if (i == N_NODES) g_feats_pad[i] = VOCAB;
    if (i < SCAN_BLKS) g_blk_agg[i] = 0;
    if (i < N_GRAPHS)  out[i] = 0.f;
}

// ---------------------------------------------------------------------------
// Single-pass scan of PADDED degrees (x8) -> rowptr + pos; re-zeros g_deg.
// 49 blocks all resident in one wave -> spin on predecessor aggregates safe.
// ---------------------------------------------------------------------------
__global__ void __launch_bounds__(1024) scan_kernel() {
    __shared__ int warp_sums[32];
    __shared__ int block_prefix;
    const int t = threadIdx.x, b = blockIdx.x;
    const int lane = t & 31, warp = t >> 5;
    if (t == 0) block_prefix = 0;

    PDL_SYNC();          // g_deg/g_blk_agg come from immediate predecessor
    PDL_TRIGGER();

    int i = b * 1024 + t;
    int d = 0;
    if (i < N_NODES) {
        d = (g_deg[i] + 7) & ~7;
        g_deg[i] = 0;
    }

    int incl = d;
#pragma unroll
    for (int off = 1; off < 32; off <<= 1) {
        int u = __shfl_up_sync(0xffffffffu, incl, off);
        if (lane >= off) incl += u;
    }
    if (lane == 31) warp_sums[warp] = incl;
    __syncthreads();

    if (warp == 0) {
        int v = warp_sums[lane];
        int w = v;
#pragma unroll
        for (int off = 1; off < 32; off <<= 1) {
            int u = __shfl_up_sync(0xffffffffu, w, off);
            if (lane >= off) w += u;
        }
        warp_sums[lane] = w;
    }
    __syncthreads();

    int wexcl = (warp > 0) ? warp_sums[warp - 1] : 0;
    int excl  = wexcl + incl - d;
    int block_total = warp_sums[31];

    if (t == 0)
        *(volatile int*)&g_blk_agg[b] = block_total + 1;

    if (t < b) {
        int v;
        do { v = *(volatile int*)&g_blk_agg[t]; } while (v == 0);
        atomicAdd(&block_prefix, v - 1);
    }
    __syncthreads();

    int r = block_prefix + excl;
    if (i < N_NODES) {
        g_rowptr[i] = r;
        g_pos[i]    = r;
    }
    if (b == SCAN_BLKS - 1 && t == 1023)
        g_rowptr[N_NODES] = block_prefix + excl + d;
}

// ---------------------------------------------------------------------------
// Scatter: one 8B (src, feat) store per edge. 8 edges/thread for deeper
// atomic-latency pipelining. Pre-sync prologue loads inputs + feats (setup
// output, >=2 back under the PDL protocol).
// ---------------------------------------------------------------------------
__global__ void scatter_kernel(const int* __restrict__ src,
                               const int* __restrict__ dst) {
    int i = blockIdx.x * blockDim.x + threadIdx.x;
    bool act = (i * 8 < N_EDGES);
    int4 s0 = {0,0,0,0}, s1 = {0,0,0,0}, d0 = {0,0,0,0}, d1 = {0,0,0,0};
    int f0 = 0, f1 = 0, f2 = 0, f3 = 0, f4 = 0, f5 = 0, f6 = 0, f7 = 0;
    if (act) {
        s0 = ((const int4*)src)[2 * i];
        s1 = ((const int4*)src)[2 * i + 1];
        d0 = ((const int4*)dst)[2 * i];
        d1 = ((const int4*)dst)[2 * i + 1];
        f0 = __ldg(&g_feats_pad[s0.x]);
        f1 = __ldg(&g_feats_pad[s0.y]);
        f2 = __ldg(&g_feats_pad[s0.z]);
        f3 = __ldg(&g_feats_pad[s0.w]);
        f4 = __ldg(&g_feats_pad[s1.x]);
        f5 = __ldg(&g_feats_pad[s1.y]);
        f6 = __ldg(&g_feats_pad[s1.z]);
        f7 = __ldg(&g_feats_pad[s1.w]);
    }
    PDL_SYNC();          // g_pos from scan (immediate predecessor)
    PDL_TRIGGER();
    if (!act) return;
    int p0 = atomicAdd(&g_pos[d0.x], 1);
    int p1 = atomicAdd(&g_pos[d0.y], 1);
    int p2 = atomicAdd(&g_pos[d0.z], 1);
    int p3 = atomicAdd(&g_pos[d0.w], 1);
    int p4 = atomicAdd(&g_pos[d1.x], 1);
    int p5 = atomicAdd(&g_pos[d1.y], 1);
    int p6 = atomicAdd(&g_pos[d1.z], 1);
    int p7 = atomicAdd(&g_pos[d1.w], 1);
    g_csr[p0] = make_int2(s0.x, f0);
    g_csr[p1] = make_int2(s0.y, f1);
    g_csr[p2] = make_int2(s0.z, f2);
    g_csr[p3] = make_int2(s0.w, f3);
    g_csr[p4] = make_int2(s1.x, f4);
    g_csr[p5] = make_int2(s1.y, f5);
    g_csr[p6] = make_int2(s1.z, f6);
    g_csr[p7] = make_int2(s1.w, f7);
}

// ---------------------------------------------------------------------------
// Unified aggregation, TEMPLATED on MODE.
//   MODE=1: z[n] = embh[feat[n]] + sum embh[csr[e].y]
//   MODE=0: z[n] = hh[n]        + sum hh[csr[e].x]
// 8 threads/node, one uint4 (8 halves) each, pairwise fp16 pre-reduction
// then fp32 accumulate; fp16 z out. Padded CSR rows (x8) -> no remainder.
// Pre-sync prologue: rowptr (scan output, >=2 back).
// ---------------------------------------------------------------------------
__device__ __forceinline__ void acc8h(float4& A, float4& B, uint4 u) {
    float2 f;
    f = __half22float2(*(const __half2*)&u.x); A.x += f.x; A.y += f.y;
    f = __half22float2(*(const __half2*)&u.y); A.z += f.x; A.w += f.y;
    f = __half22float2(*(const __half2*)&u.z); B.x += f.x; B.y += f.y;
    f = __half22float2(*(const __half2*)&u.w); B.z += f.x; B.w += f.y;
}

__device__ __forceinline__ uint4 hadd4(uint4 a, uint4 b) {
    uint4 r;
    *(__half2*)&r.x = __hadd2(*(const __half2*)&a.x, *(const __half2*)&b.x);
    *(__half2*)&r.y = __hadd2(*(const __half2*)&a.y, *(const __half2*)&b.y);
    *(__half2*)&r.z = __hadd2(*(const __half2*)&a.z, *(const __half2*)&b.z);
    *(__half2*)&r.w = __hadd2(*(const __half2*)&a.w, *(const __half2*)&b.w);
    return r;
}

template <int MODE>
__global__ void __launch_bounds__(256)
agg_kernel_t() {
    int i = blockIdx.x * blockDim.x + threadIdx.x;
    bool act = (i < N_NODES * 8);
    int n = (act ? i : 0) >> 3;
    int c = i & 7;
    const uint4* tab = MODE ? (const uint4*)g_embh : (const uint4*)g_hh;

    // pre-sync: rowptr is >=2 kernels back under the PDL protocol
    int e = 0, end = 0;
    if (act) {
        e   = __ldg(&g_rowptr[n]);
        end = __ldg(&g_rowptr[n + 1]);
    }
    PDL_SYNC();          // csr (agg<1>) / hh (agg<0>) from immediate pred
    PDL_TRIGGER();
    if (!act) return;

    float4 A = {0.f, 0.f, 0.f, 0.f}, B = {0.f, 0.f, 0.f, 0.f};
    int self = MODE ? __ldg(&g_feats_pad[n]) : n;
    acc8h(A, B, tab[self * 8 + c]);

    for (; e < end; e += 8) {
        int4 p0 = *(const int4*)&g_csr[e];       // (s,f, s,f) edges e,e+1
        int4 p1 = *(const int4*)&g_csr[e + 2];
        int4 p2 = *(const int4*)&g_csr[e + 4];
        int4 p3 = *(const int4*)&g_csr[e + 6];
        int s0 = MODE ? p0.y : p0.x;
        int s1 = MODE ? p0.w : p0.z;
        int s2 = MODE ? p1.y : p1.x;
        int s3 = MODE ? p1.w : p1.z;
        int s4 = MODE ? p2.y : p2.x;
        int s5 = MODE ? p2.w : p2.z;
        int s6 = MODE ? p3.y : p3.x;
        int s7 = MODE ? p3.w : p3.z;
        uint4 u0 = tab[s0 * 8 + c];
        uint4 u1 = tab[s1 * 8 + c];
        uint4 u2 = tab[s2 * 8 + c];
        uint4 u3 = tab[s3 * 8 + c];
        uint4 u4 = tab[s4 * 8 + c];
        uint4 u5 = tab[s5 * 8 + c];
        uint4 u6 = tab[s6 * 8 + c];
        uint4 u7 = tab[s7 * 8 + c];
        uint4 v0 = hadd4(u0, u1);
        uint4 v1 = hadd4(u2, u3);
        uint4 v2 = hadd4(u4, u5);
        uint4 v3 = hadd4(u6, u7);
        acc8h(A, B, v0);
        acc8h(A, B, v1);
        acc8h(A, B, v2);
        acc8h(A, B, v3);
    }
    __half2 q0 = __floats2half2_rn(A.x, A.y);
    __half2 q1 = __floats2half2_rn(A.z, A.w);
    __half2 q2 = __floats2half2_rn(B.x, B.y);
    __half2 q3 = __floats2half2_rn(B.z, B.w);
    ((uint4*)g_zh)[n * 8 + c] = make_uint4(*(unsigned*)&q0, *(unsigned*)&q1,
                                           *(unsigned*)&q2, *(unsigned*)&q3);
}

// ---------------------------------------------------------------------------
// MLP via tensor cores (HMMA m16n8k16, fp16 in / fp32 accum):
//   h = relu(z@W1+b1)@W2 + b2.
// 128 threads (4 warps), 128 nodes/block. Pre-sync prologue stages WEIGHTS
// (setup output, >=2 back) overlapping the predecessor agg's tail; z staged
// after sync. LAST layer: fused pool+head.
// ---------------------------------------------------------------------------
#define WS 72   // padded row stride in halves (144B -> conflict-free ldmatrix)

#define LDSM_X4(r0, r1, r2, r3, a) \
    asm volatile("ldmatrix.sync.aligned.m8n8.x4.shared.b16 {%0,%1,%2,%3}, [%4];" \
                 : "=r"(r0), "=r"(r1), "=r"(r2), "=r"(r3) : "r"(a))
#define LDSM_X4T(r0, r1, r2, r3, a) \
    asm volatile("ldmatrix.sync.aligned.m8n8.x4.trans.shared.b16 {%0,%1,%2,%3}, [%4];" \
                 : "=r"(r0), "=r"(r1), "=r"(r2), "=r"(r3) : "r"(a))
#define MMA16816(c, a, b) \
    asm volatile("mma.sync.aligned.m16n8k16.row.col.f32.f16.f16.f32 " \
                 "{%0,%1,%2,%3}, {%4,%5,%6,%7}, {%8,%9}, {%0,%1,%2,%3};" \
                 : "+f"((c)[0]), "+f"((c)[1]), "+f"((c)[2]), "+f"((c)[3]) \
                 : "r"((a)[0]), "r"((a)[1]), "r"((a)[2]), "r"((a)[3]), \
                   "r"((b)[0]), "r"((b)[1]))

__global__ void __launch_bounds__(128)
mlp_kernel(const float* __restrict__ b1, const float* __restrict__ b2,
           int layer, int last,
           const int* __restrict__ gids, const float* __restrict__ Wr,
           float* __restrict__ out) {
    __shared__ __align__(16) __half sW1[HID * WS];
    __shared__ __align__(16) __half sW2[HID * WS];
    __shared__ __align__(16) __half sZ[NPB * WS];

    const int tid  = threadIdx.x;
    const int lane = tid & 31;
    const int w    = tid >> 5;
    const int nbase = blockIdx.x * NPB;

    // ---- PRE-SYNC: stage fp16 weights (setup output, >=2 back) ----
    {
        const uint4* w1g = (const uint4*)(g_w1h + layer * HID * HID);
        const uint4* w2g = (const uint4*)(g_w2h + layer * HID * HID);
#pragma unroll
        for (int idx = tid; idx < 512; idx += 128) {
            int r = idx >> 3, c = idx & 7;
            *(uint4*)&sW1[r * WS + c * 8] = w1g[idx];
            *(uint4*)&sW2[r * WS + c * 8] = w2g[idx];
        }
    }
    PDL_SYNC();          // z from immediate predecessor agg
    PDL_TRIGGER();

    // ---- stage z tile (one 128B row per thread) ----
    {
        int n = nbase + tid;
        if (n < N_NODES) {
            const uint4* zr = (const uint4*)(g_zh + n * HID);
#pragma unroll
            for (int q = 0; q < 8; q++)
                *(uint4*)&sZ[tid * WS + q * 8] = zr[q];
        } else {
            uint4 zz = make_uint4(0u, 0u, 0u, 0u);
#pragma unroll
            for (int q = 0; q < 8; q++)
                *(uint4*)&sZ[tid * WS + q * 8] = zz;
        }
    }
    __syncthreads();

    const float* b1g = b1 + layer * HID;
    const float* b2g = b2 + layer * HID;

    float acc[2][8][4];
    unsigned ya[2][8][2];   // relu(GEMM1) as fp16 A-fragments

    // ================= GEMM 1: Y = relu(Z @ W1 + b1) =================
#pragma unroll
    for (int nt = 0; nt < 8; nt++) {
        int col = nt * 8 + (lane & 3) * 2;
        float v0 = __ldg(b1g + col), v1 = __ldg(b1g + col + 1);
#pragma unroll
        for (int mt = 0; mt < 2; mt++) {
            acc[mt][nt][0] = v0; acc[mt][nt][1] = v1;
            acc[mt][nt][2] = v0; acc[mt][nt][3] = v1;
        }
    }
#pragma unroll
    for (int ks = 0; ks < 4; ks++) {
        unsigned a[2][4], bf[8][2];
#pragma unroll
        for (int mt = 0; mt < 2; mt++) {
            int row = 32 * w + mt * 16 + (lane & 15);
            int ch  = ks * 16 + ((lane >> 4) << 3);
            LDSM_X4(a[mt][0], a[mt][1], a[mt][2], a[mt][3],
                    su32(&sZ[row * WS + ch]));
        }
#pragma unroll
        for (int ntp = 0; ntp < 4; ntp++) {
            int kr = ks * 16 + (((lane >> 3) & 1) << 3) + (lane & 7);
            int nc = ntp * 16 + ((lane >> 4) << 3);
            LDSM_X4T(bf[2 * ntp][0], bf[2 * ntp][1],
                     bf[2 * ntp + 1][0], bf[2 * ntp + 1][1],
                     su32(&sW1[kr * WS + nc]));
        }
#pragma unroll
        for (int mt = 0; mt < 2; mt++)
#pragma unroll
            for (int nt = 0; nt < 8; nt++)
                MMA16816(acc[mt][nt], a[mt], bf[nt]);
    }
    // relu + pack fp16 (C layout == A layout)
#pragma unroll
    for (int mt = 0; mt < 2; mt++)
#pragma unroll
        for (int nt = 0; nt < 8; nt++) {
            __half2 y0 = __floats2half2_rn(fmaxf(acc[mt][nt][0], 0.f),
                                           fmaxf(acc[mt][nt][1], 0.f));
            __half2 y1 = __floats2half2_rn(fmaxf(acc[mt][nt][2], 0.f),
                                           fmaxf(acc[mt][nt][3], 0.f));
            ya[mt][nt][0] = *(unsigned*)&y0;
            ya[mt][nt][1] = *(unsigned*)&y1;
        }

    // ================= GEMM 2: H = Y @ W2 + b2 =================
#pragma unroll
    for (int nt = 0; nt < 8; nt++) {
        int col = nt * 8 + (lane & 3) * 2;
        float v0 = __ldg(b2g + col), v1 = __ldg(b2g + col + 1);
#pragma unroll
        for (int mt = 0; mt < 2; mt++) {
            acc[mt][nt][0] = v0; acc[mt][nt][1] = v1;
            acc[mt][nt][2] = v0; acc[mt][nt][3] = v1;
        }
    }
#pragma unroll
    for (int kt = 0; kt < 4; kt++) {
        unsigned bf[8][2];
#pragma unroll
        for (int ntp = 0; ntp < 4; ntp++) {
            int kr = kt * 16 + (((lane >> 3) & 1) << 3) + (lane & 7);
            int nc = ntp * 16 + ((lane >> 4) << 3);
            LDSM_X4T(bf[2 * ntp][0], bf[2 * ntp][1],
                     bf[2 * ntp + 1][0], bf[2 * ntp + 1][1],
                     su32(&sW2[kr * WS + nc]));
        }
#pragma unroll
        for (int mt = 0; mt < 2; mt++) {
            unsigned a2[4] = { ya[mt][2 * kt][0],     ya[mt][2 * kt][1],
                               ya[mt][2 * kt + 1][0], ya[mt][2 * kt + 1][1] };
#pragma unroll
            for (int nt = 0; nt < 8; nt++)
                MMA16816(acc[mt][nt], a2, bf[nt]);
        }
    }

    if (!last) {
        // store h fp16: thread owns (row0, row0+8) x col pairs per tile
#pragma unroll
        for (int mt = 0; mt < 2; mt++) {
            int row0 = nbase + 32 * w + mt * 16 + (lane >> 2);
#pragma unroll
            for (int nt = 0; nt < 8; nt++) {
                int col = nt * 8 + (lane & 3) * 2;
                if (row0 < N_NODES) {
                    __half2 v = __floats2half2_rn(acc[mt][nt][0], acc[mt][nt][1]);
                    *(__half2*)&g_hh[row0 * HID + col] = v;
                }
                if (row0 + 8 < N_NODES) {
                    __half2 v = __floats2half2_rn(acc[mt][nt][2], acc[mt][nt][3]);
                    *(__half2*)&g_hh[(row0 + 8) * HID + col] = v;
                }
            }
        }
    } else {
        // fused pool + head: dot rows with Wr, reduce over 4 col-lanes
#pragma unroll
        for (int mt = 0; mt < 2; mt++) {
            float d0 = 0.f, d1 = 0.f;
#pragma unroll
            for (int nt = 0; nt < 8; nt++) {
                int col = nt * 8 + (lane & 3) * 2;
                float wr0 = __ldg(Wr + col), wr1 = __ldg(Wr + col + 1);
                d0 = fmaf(acc[mt][nt][0], wr0, fmaf(acc[mt][nt][1], wr1, d0));
                d1 = fmaf(acc[mt][nt][2], wr0, fmaf(acc[mt][nt][3], wr1, d1));
            }
            d0 += __shfl_xor_sync(0xffffffffu, d0, 1);
            d0 += __shfl_xor_sync(0xffffffffu, d0, 2);
            d1 += __shfl_xor_sync(0xffffffffu, d1, 1);
            d1 += __shfl_xor_sync(0xffffffffu, d1, 2);
            if ((lane & 3) == 0) {
                int row0 = nbase + 32 * w + mt * 16 + (lane >> 2);
                if (row0 < N_NODES)
                    atomicAdd(out + __ldg(gids + row0), d0);
                if (row0 + 8 < N_NODES)
                    atomicAdd(out + __ldg(gids + row0 + 8), d1);
            }
        }
    }
}

// ---------------------------------------------------------------------------
// Host: launch everything with Programmatic Stream Serialization (PDL).
// ---------------------------------------------------------------------------
template <typename K, typename... Args>
static void launch_pdl(K k, int grid, int block, Args... args) {
    cudaLaunchAttribute at[1];
    at[0].id = cudaLaunchAttributeProgrammaticStreamSerialization;
    at[0].val.programmaticStreamSerializationAllowed = 1;
    cudaLaunchConfig_t cfg = {};
    cfg.gridDim = dim3(grid, 1, 1);
    cfg.blockDim = dim3(block, 1, 1);
    cfg.dynamicSmemBytes = 0;
    cfg.stream = 0;
    cfg.attrs = at;
    cfg.numAttrs = 1;
    cudaLaunchKernelEx(&cfg, k, args...);
}

extern "C" void kernel_launch(void* const* d_in, const int* in_sizes, int n_in,
                              void* d_out, int out_size) {
    const int*   feats = (const int*)d_in[0];
    const int*   src   = (const int*)d_in[1];
    const int*   dst   = (const int*)d_in[2];
    const int*   gids  = (const int*)d_in[3];
    const float* emb   = (const float*)d_in[4];
    const float* W1    = (const float*)d_in[5];
    const float* b1    = (const float*)d_in[6];
    const float* W2    = (const float*)d_in[7];
    const float* b2    = (const float*)d_in[8];
    const float* Wr    = (const float*)d_in[9];
    float* out = (float*)d_out;

    const int sblk = (CSR_CAP / 4 + 255) / 256;
    const int cblk = (N_EDGES / 8 + 255) / 256;
    const int ablk = (N_NODES * 8 + 255) / 256;
    const int mblk = (N_NODES + NPB - 1) / NPB;

    launch_pdl(setup_kernel, sblk, 256, dst, feats, emb, W1, W2, out);
    launch_pdl(scan_kernel, SCAN_BLKS, 1024);
    launch_pdl(scatter_kernel, cblk, 256, src, dst);

    launch_pdl(agg_kernel_t<1>, ablk, 256);
    launch_pdl(mlp_kernel, mblk, 128, b1, b2, 0, 0, gids, Wr, out);
    launch_pdl(agg_kernel_t<0>, ablk, 256);
    launch_pdl(mlp_kernel, mblk, 128, b1, b2, 1, 0, gids, Wr, out);
    launch_pdl(agg_kernel_t<0>, ablk, 256);
    launch_pdl(mlp_kernel, mblk, 128, b1, b2, 2, 1, gids, Wr, out);
}